// round 13
// baseline (speedup 1.0000x reference)
#include <cuda_runtime.h>
#include <cuda_bf16.h>
#include <math.h>

// Problem constants
#define BB 2
#define TT 1024
#define DD 768
#define HH 12
#define HD 64
#define LL 8
#define FF 3072
#define VV 1024
#define BT (BB*TT)          // 2048
#define D3 (3*DD)           // 2304

// ---------------------------------------------------------------------------
// Scratch buffers (device globals; no allocation allowed)
// ---------------------------------------------------------------------------
__device__ float g_x  [BT * DD];   // residual stream
__device__ float g_h  [BT * DD];   // LN output / final-LN output
__device__ float g_qkv[BT * D3];   // qkv projection
__device__ float g_y  [BT * DD];   // attention output
__device__ float g_f1 [BT * FF];   // FFN hidden

// ---------------------------------------------------------------------------
// Embedding: x[b,t,:] = tok_emb[ids[b,t],:] + pos_emb[t,:]
// ---------------------------------------------------------------------------
__global__ void embed_kernel(const int* __restrict__ ids,
                             const float* __restrict__ tok,
                             const float* __restrict__ pos,
                             float* __restrict__ x)
{
    int idx = blockIdx.x * blockDim.x + threadIdx.x;   // < BT*DD
    int bt = idx / DD;
    int d  = idx - bt * DD;
    int t  = bt & (TT - 1);
    x[idx] = tok[(size_t)ids[bt] * DD + d] + pos[(size_t)t * DD + d];
}

// ---------------------------------------------------------------------------
// LayerNorm (two-pass, exact): one CTA per row, 256 threads, D=768
// ---------------------------------------------------------------------------
__global__ __launch_bounds__(256) void ln_kernel(const float* __restrict__ x,
                                                 const float* __restrict__ w,
                                                 const float* __restrict__ b,
                                                 float* __restrict__ out)
{
    int row = blockIdx.x;
    int tid = threadIdx.x;
    const float* xr = x + (size_t)row * DD;
    __shared__ float red[256];

    float v0 = xr[tid], v1 = xr[tid + 256], v2 = xr[tid + 512];

    red[tid] = v0 + v1 + v2;
    __syncthreads();
    #pragma unroll
    for (int off = 128; off > 0; off >>= 1) {
        if (tid < off) red[tid] += red[tid + off];
        __syncthreads();
    }
    float mu = red[0] * (1.0f / DD);
    __syncthreads();

    float d0 = v0 - mu, d1 = v1 - mu, d2 = v2 - mu;
    red[tid] = d0 * d0 + d1 * d1 + d2 * d2;
    __syncthreads();
    #pragma unroll
    for (int off = 128; off > 0; off >>= 1) {
        if (tid < off) red[tid] += red[tid + off];
        __syncthreads();
    }
    float rstd = rsqrtf(red[0] * (1.0f / DD) + 1e-5f);

    float* orow = out + (size_t)row * DD;
    orow[tid]       = d0 * rstd * w[tid]       + b[tid];
    orow[tid + 256] = d1 * rstd * w[tid + 256] + b[tid + 256];
    orow[tid + 512] = d2 * rstd * w[tid + 512] + b[tid + 512];
}

// ---------------------------------------------------------------------------
// SGEMM: C[M,N] = A[M,K] @ B  (B either [K,N] or, if TB, [N,K] accessed ^T)
// 128x128 tile, BK=16, 8x8 per thread, 256 threads.
// EPI: 0 = plain store
//      1 = +bias, exact GELU
//      2 = +res (residual add; res may alias C)
//      3 = +bias +res
// ---------------------------------------------------------------------------
#define BM 128
#define BN 128
#define BK 16

template<int EPI, bool TB>
__global__ __launch_bounds__(256) void sgemm(const float* __restrict__ A,
                                             const float* __restrict__ Bm,
                                             const float* __restrict__ bias,
                                             const float* __restrict__ res,
                                             float* __restrict__ C,
                                             int M, int N, int K)
{
    __shared__ float As[BK][BM];
    __shared__ float Bs[BK][BN];

    int tid  = threadIdx.x;
    int brow = blockIdx.y * BM;
    int bcol = blockIdx.x * BN;
    int ty = tid >> 4;   // 0..15
    int tx = tid & 15;   // 0..15

    float acc[8][8];
    #pragma unroll
    for (int i = 0; i < 8; i++)
        #pragma unroll
        for (int j = 0; j < 8; j++) acc[i][j] = 0.0f;

    for (int k0 = 0; k0 < K; k0 += BK) {
        // Load A tile [BM x BK], store transposed As[k][m]
        #pragma unroll
        for (int i = 0; i < 2; i++) {
            int s  = tid + i * 256;        // 0..511
            int r  = s >> 2;               // 0..127
            int c4 = (s & 3) * 4;          // 0,4,8,12
            float4 v = *(const float4*)&A[(size_t)(brow + r) * K + k0 + c4];
            As[c4 + 0][r] = v.x; As[c4 + 1][r] = v.y;
            As[c4 + 2][r] = v.z; As[c4 + 3][r] = v.w;
        }
        // Load B tile
        if (!TB) {
            #pragma unroll
            for (int i = 0; i < 2; i++) {
                int s  = tid + i * 256;
                int r  = s >> 5;            // 0..15
                int c4 = (s & 31) * 4;      // 0..124
                *(float4*)&Bs[r][c4] =
                    *(const float4*)&Bm[(size_t)(k0 + r) * N + bcol + c4];
            }
        } else {
            #pragma unroll
            for (int i = 0; i < 2; i++) {
                int s  = tid + i * 256;
                int r  = s >> 2;            // 0..127  (n index)
                int c4 = (s & 3) * 4;       // k offset
                float4 v = *(const float4*)&Bm[(size_t)(bcol + r) * K + k0 + c4];
                Bs[c4 + 0][r] = v.x; Bs[c4 + 1][r] = v.y;
                Bs[c4 + 2][r] = v.z; Bs[c4 + 3][r] = v.w;
            }
        }
        __syncthreads();

        #pragma unroll
        for (int kk = 0; kk < BK; kk++) {
            float a[8], bv[8];
            #pragma unroll
            for (int i = 0; i < 8; i++) a[i]  = As[kk][ty * 8 + i];
            #pragma unroll
            for (int j = 0; j < 8; j++) bv[j] = Bs[kk][tx * 8 + j];
            #pragma unroll
            for (int i = 0; i < 8; i++)
                #pragma unroll
                for (int j = 0; j < 8; j++)
                    acc[i][j] += a[i] * bv[j];
        }
        __syncthreads();
    }

    // Epilogue
    #pragma unroll
    for (int i = 0; i < 8; i++) {
        int r = brow + ty * 8 + i;
        #pragma unroll
        for (int j = 0; j < 8; j++) {
            int c = bcol + tx * 8 + j;
            float v = acc[i][j];
            if (EPI == 1) {
                v += bias[c];
                v = 0.5f * v * (1.0f + erff(v * 0.70710678118654752f));
            } else if (EPI == 2) {
                v += res[(size_t)r * N + c];
            } else if (EPI == 3) {
                v += bias[c] + res[(size_t)r * N + c];
            }
            C[(size_t)r * N + c] = v;
        }
    }
}

// ---------------------------------------------------------------------------
// Causal attention, fp32 flash-style.
// grid = (T/64, B*H), 256 threads. Each CTA: 64 q-rows for one (b,h).
// Online softmax, 4x4 register tiles on a 16x16 thread grid.
// Dynamic smem: Qs,Ks,Vs,Ps each [64][68] floats = 69632 B total.
// ---------------------------------------------------------------------------
#define APAD 68
#define ATTN_SMEM (4 * 64 * APAD * (int)sizeof(float))

__global__ __launch_bounds__(256) void attn_kernel(const float* __restrict__ qkv,
                                                   float* __restrict__ y)
{
    extern __shared__ float sm[];
    float (*Qs)[APAD] = (float(*)[APAD])(sm);
    float (*Ks)[APAD] = (float(*)[APAD])(sm + 1 * 64 * APAD);  // stored [d][c]
    float (*Vs)[APAD] = (float(*)[APAD])(sm + 2 * 64 * APAD);  // stored [j][d]
    float (*Ps)[APAD] = (float(*)[APAD])(sm + 3 * 64 * APAD);  // stored [r][j]

    int qb = blockIdx.x;             // q tile 0..15
    int bh = blockIdx.y;             // 0..23
    int b  = bh / HH, h = bh % HH;
    int tid = threadIdx.x;
    int ty = tid >> 4, tx = tid & 15;

    const float* base = qkv + (size_t)b * TT * D3 + h * HD;

    // Load Q tile [64 x 64]
    #pragma unroll
    for (int i = 0; i < 4; i++) {
        int s  = tid + i * 256;       // 0..1023
        int r  = s >> 4;              // 0..63
        int c4 = (s & 15) * 4;        // 0..60
        *(float4*)&Qs[r][c4] =
            *(const float4*)&base[(size_t)(qb * 64 + r) * D3 + c4];
    }

    float o[4][4];
    float m_run[4], l_run[4];
    #pragma unroll
    for (int i = 0; i < 4; i++) {
        m_run[i] = -INFINITY; l_run[i] = 0.0f;
        #pragma unroll
        for (int j = 0; j < 4; j++) o[i][j] = 0.0f;
    }
    const float scale = 0.125f;      // 1/sqrt(64)

    for (int kb = 0; kb <= qb; kb++) {
        __syncthreads();   // prior P@V done with Ks/Vs; Qs visible after next sync
        // K tile transposed -> Ks[d][c]; V tile natural -> Vs[j][d]
        #pragma unroll
        for (int i = 0; i < 4; i++) {
            int s  = tid + i * 256;
            int r  = s >> 4;
            int c4 = (s & 15) * 4;
            float4 kv = *(const float4*)&base[DD     + (size_t)(kb * 64 + r) * D3 + c4];
            Ks[c4 + 0][r] = kv.x; Ks[c4 + 1][r] = kv.y;
            Ks[c4 + 2][r] = kv.z; Ks[c4 + 3][r] = kv.w;
            *(float4*)&Vs[r][c4] =
                *(const float4*)&base[2 * DD + (size_t)(kb * 64 + r) * D3 + c4];
        }
        __syncthreads();

        // S = Q @ K^T  (4x4 per thread)
        float s4[4][4];
        #pragma unroll
        for (int i = 0; i < 4; i++)
            #pragma unroll
            for (int j = 0; j < 4; j++) s4[i][j] = 0.0f;
        #pragma unroll
        for (int d = 0; d < 64; d++) {
            float a[4], bv[4];
            #pragma unroll
            for (int i = 0; i < 4; i++) a[i]  = Qs[ty * 4 + i][d];
            #pragma unroll
            for (int j = 0; j < 4; j++) bv[j] = Ks[d][tx * 4 + j];
            #pragma unroll
            for (int i = 0; i < 4; i++)
                #pragma unroll
                for (int j = 0; j < 4; j++)
                    s4[i][j] += a[i] * bv[j];
        }

        bool diag = (kb == qb);
        #pragma unroll
        for (int i = 0; i < 4; i++)
            #pragma unroll
            for (int j = 0; j < 4; j++) {
                float v = s4[i][j] * scale;
                if (diag && (tx * 4 + j) > (ty * 4 + i)) v = -INFINITY;
                s4[i][j] = v;
            }

        // Online softmax update per row (16 tx-threads per 4-row group)
        #pragma unroll
        for (int i = 0; i < 4; i++) {
            float mx = fmaxf(fmaxf(s4[i][0], s4[i][1]), fmaxf(s4[i][2], s4[i][3]));
            #pragma unroll
            for (int off = 8; off >= 1; off >>= 1)
                mx = fmaxf(mx, __shfl_xor_sync(0xffffffffu, mx, off, 16));
            float nm    = fmaxf(m_run[i], mx);
            float alpha = expf(m_run[i] - nm);
            float rs = 0.0f;
            #pragma unroll
            for (int j = 0; j < 4; j++) {
                float p = expf(s4[i][j] - nm);
                s4[i][j] = p;
                rs += p;
            }
            #pragma unroll
            for (int off = 8; off >= 1; off >>= 1)
                rs += __shfl_xor_sync(0xffffffffu, rs, off, 16);
            l_run[i] = l_run[i] * alpha + rs;
            m_run[i] = nm;
            #pragma unroll
            for (int j = 0; j < 4; j++) o[i][j] *= alpha;
        }

        // Publish P, then O += P @ V
        #pragma unroll
        for (int i = 0; i < 4; i++)
            *(float4*)&Ps[ty * 4 + i][tx * 4] =
                make_float4(s4[i][0], s4[i][1], s4[i][2], s4[i][3]);
        __syncthreads();

        #pragma unroll
        for (int jj = 0; jj < 64; jj++) {
            float pv[4], vv[4];
            #pragma unroll
            for (int i = 0; i < 4; i++) pv[i] = Ps[ty * 4 + i][jj];
            #pragma unroll
            for (int j = 0; j < 4; j++) vv[j] = Vs[jj][tx * 4 + j];
            #pragma unroll
            for (int i = 0; i < 4; i++)
                #pragma unroll
                for (int j = 0; j < 4; j++)
                    o[i][j] += pv[i] * vv[j];
        }
    }

    // Normalize and store: y[b, t, h*64 + d]
    float* ybase = y + (size_t)b * TT * DD + h * HD;
    #pragma unroll
    for (int i = 0; i < 4; i++) {
        float inv = 1.0f / l_run[i];
        int r = qb * 64 + ty * 4 + i;
        #pragma unroll
        for (int j = 0; j < 4; j++)
            ybase[(size_t)r * DD + tx * 4 + j] = o[i][j] * inv;
    }
}

// ---------------------------------------------------------------------------
// Host orchestration
// ---------------------------------------------------------------------------
extern "C" void kernel_launch(void* const* d_in, const int* in_sizes, int n_in,
                              void* d_out, int out_size)
{
    (void)in_sizes; (void)n_in; (void)out_size;

    const int*   ids  = (const int*)  d_in[0];
    const float* tok  = (const float*)d_in[1];
    const float* pos  = (const float*)d_in[2];
    const float* ln1w = (const float*)d_in[3];
    const float* ln1b = (const float*)d_in[4];
    const float* qkvw = (const float*)d_in[5];
    const float* outw = (const float*)d_in[6];
    const float* ln2w = (const float*)d_in[7];
    const float* ln2b = (const float*)d_in[8];
    const float* w1   = (const float*)d_in[9];
    const float* b1   = (const float*)d_in[10];
    const float* w2   = (const float*)d_in[11];
    const float* b2   = (const float*)d_in[12];
    const float* lnfw = (const float*)d_in[13];
    const float* lnfb = (const float*)d_in[14];
    float* out = (float*)d_out;

    float *x, *h, *qkv, *y, *f1;
    cudaGetSymbolAddress((void**)&x,   g_x);
    cudaGetSymbolAddress((void**)&h,   g_h);
    cudaGetSymbolAddress((void**)&qkv, g_qkv);
    cudaGetSymbolAddress((void**)&y,   g_y);
    cudaGetSymbolAddress((void**)&f1,  g_f1);

    cudaFuncSetAttribute(attn_kernel,
                         cudaFuncAttributeMaxDynamicSharedMemorySize, ATTN_SMEM);

    // Embedding
    embed_kernel<<<(BT * DD) / 256, 256>>>(ids, tok, pos, x);

    for (int l = 0; l < LL; l++) {
        // LN1
        ln_kernel<<<BT, 256>>>(x, ln1w + l * DD, ln1b + l * DD, h);
        // QKV projection: [2048,768] @ [768,2304]
        sgemm<0, false><<<dim3(D3 / BN, BT / BM), 256>>>(
            h, qkvw + (size_t)l * DD * D3, nullptr, nullptr, qkv, BT, D3, DD);
        // Attention
        attn_kernel<<<dim3(TT / 64, BB * HH), 256, ATTN_SMEM>>>(qkv, y);
        // Out projection + residual (in-place on x)
        sgemm<2, false><<<dim3(DD / BN, BT / BM), 256>>>(
            y, outw + (size_t)l * DD * DD, nullptr, x, x, BT, DD, DD);
        // LN2
        ln_kernel<<<BT, 256>>>(x, ln2w + l * DD, ln2b + l * DD, h);
        // FFN1 + bias + exact GELU
        sgemm<1, false><<<dim3(FF / BN, BT / BM), 256>>>(
            h, w1 + (size_t)l * DD * FF, b1 + (size_t)l * FF, nullptr, f1, BT, FF, DD);
        // FFN2 + bias + residual (in-place on x)
        sgemm<3, false><<<dim3(DD / BN, BT / BM), 256>>>(
            f1, w2 + (size_t)l * FF * DD, b2 + (size_t)l * DD, x, x, BT, DD, FF);
    }

    // Final LN
    ln_kernel<<<BT, 256>>>(x, lnfw, lnfb, h);
    // Tied LM head: [2048,768] @ tok_emb[1024,768]^T
    sgemm<0, true><<<dim3(VV / BN, BT / BM), 256>>>(
        h, tok, nullptr, nullptr, out, BT, VV, DD);
}

// round 14
// speedup vs baseline: 1.0015x; 1.0015x over previous
#include <cuda_runtime.h>
#include <cuda_bf16.h>
#include <math.h>

// Problem constants
#define BB 2
#define TT 1024
#define DD 768
#define HH 12
#define HD 64
#define LL 8
#define FF 3072
#define VV 1024
#define BT (BB*TT)          // 2048
#define D3 (3*DD)           // 2304

// ---------------------------------------------------------------------------
// Scratch buffers (device globals; no allocation allowed)
// ---------------------------------------------------------------------------
__device__ float g_x  [BT * DD];   // residual stream
__device__ float g_h  [BT * DD];   // LN output / final-LN output
__device__ float g_qkv[BT * D3];   // qkv projection
__device__ float g_y  [BT * DD];   // attention output
__device__ float g_f1 [BT * FF];   // FFN hidden

// ---------------------------------------------------------------------------
// Embedding: x[b,t,:] = tok_emb[ids[b,t],:] + pos_emb[t,:]
// ---------------------------------------------------------------------------
__global__ void embed_kernel(const int* __restrict__ ids,
                             const float* __restrict__ tok,
                             const float* __restrict__ pos,
                             float* __restrict__ x)
{
    int idx = blockIdx.x * blockDim.x + threadIdx.x;   // < BT*DD
    int bt = idx / DD;
    int d  = idx - bt * DD;
    int t  = bt & (TT - 1);
    x[idx] = tok[(size_t)ids[bt] * DD + d] + pos[(size_t)t * DD + d];
}

// ---------------------------------------------------------------------------
// LayerNorm (two-pass, exact): one CTA per row, 256 threads, D=768
// ---------------------------------------------------------------------------
__global__ __launch_bounds__(256) void ln_kernel(const float* __restrict__ x,
                                                 const float* __restrict__ w,
                                                 const float* __restrict__ b,
                                                 float* __restrict__ out)
{
    int row = blockIdx.x;
    int tid = threadIdx.x;
    const float* xr = x + (size_t)row * DD;
    __shared__ float red[256];

    float v0 = xr[tid], v1 = xr[tid + 256], v2 = xr[tid + 512];

    red[tid] = v0 + v1 + v2;
    __syncthreads();
    #pragma unroll
    for (int off = 128; off > 0; off >>= 1) {
        if (tid < off) red[tid] += red[tid + off];
        __syncthreads();
    }
    float mu = red[0] * (1.0f / DD);
    __syncthreads();

    float d0 = v0 - mu, d1 = v1 - mu, d2 = v2 - mu;
    red[tid] = d0 * d0 + d1 * d1 + d2 * d2;
    __syncthreads();
    #pragma unroll
    for (int off = 128; off > 0; off >>= 1) {
        if (tid < off) red[tid] += red[tid + off];
        __syncthreads();
    }
    float rstd = rsqrtf(red[0] * (1.0f / DD) + 1e-5f);

    float* orow = out + (size_t)row * DD;
    orow[tid]       = d0 * rstd * w[tid]       + b[tid];
    orow[tid + 256] = d1 * rstd * w[tid + 256] + b[tid + 256];
    orow[tid + 512] = d2 * rstd * w[tid + 512] + b[tid + 512];
}

// ---------------------------------------------------------------------------
// SGEMM: C[M,N] = A[M,K] @ B  (B either [K,N] or, if TB, [N,K] accessed ^T)
// 128x128 tile, BK=16, 8x8 per thread, 256 threads.
// EPI: 0 = plain store
//      1 = +bias, exact GELU
//      2 = +res (residual add; res may alias C)
//      3 = +bias +res
// ---------------------------------------------------------------------------
#define BM 128
#define BN 128
#define BK 16

template<int EPI, bool TB>
__global__ __launch_bounds__(256) void sgemm(const float* __restrict__ A,
                                             const float* __restrict__ Bm,
                                             const float* __restrict__ bias,
                                             const float* __restrict__ res,
                                             float* __restrict__ C,
                                             int M, int N, int K)
{
    __shared__ float As[BK][BM];
    __shared__ float Bs[BK][BN];

    int tid  = threadIdx.x;
    int brow = blockIdx.y * BM;
    int bcol = blockIdx.x * BN;
    int ty = tid >> 4;   // 0..15
    int tx = tid & 15;   // 0..15

    float acc[8][8];
    #pragma unroll
    for (int i = 0; i < 8; i++)
        #pragma unroll
        for (int j = 0; j < 8; j++) acc[i][j] = 0.0f;

    for (int k0 = 0; k0 < K; k0 += BK) {
        // Load A tile [BM x BK], store transposed As[k][m]
        #pragma unroll
        for (int i = 0; i < 2; i++) {
            int s  = tid + i * 256;        // 0..511
            int r  = s >> 2;               // 0..127
            int c4 = (s & 3) * 4;          // 0,4,8,12
            float4 v = *(const float4*)&A[(size_t)(brow + r) * K + k0 + c4];
            As[c4 + 0][r] = v.x; As[c4 + 1][r] = v.y;
            As[c4 + 2][r] = v.z; As[c4 + 3][r] = v.w;
        }
        // Load B tile
        if (!TB) {
            #pragma unroll
            for (int i = 0; i < 2; i++) {
                int s  = tid + i * 256;
                int r  = s >> 5;            // 0..15
                int c4 = (s & 31) * 4;      // 0..124
                *(float4*)&Bs[r][c4] =
                    *(const float4*)&Bm[(size_t)(k0 + r) * N + bcol + c4];
            }
        } else {
            #pragma unroll
            for (int i = 0; i < 2; i++) {
                int s  = tid + i * 256;
                int r  = s >> 2;            // 0..127  (n index)
                int c4 = (s & 3) * 4;       // k offset
                float4 v = *(const float4*)&Bm[(size_t)(bcol + r) * K + k0 + c4];
                Bs[c4 + 0][r] = v.x; Bs[c4 + 1][r] = v.y;
                Bs[c4 + 2][r] = v.z; Bs[c4 + 3][r] = v.w;
            }
        }
        __syncthreads();

        #pragma unroll
        for (int kk = 0; kk < BK; kk++) {
            float a[8], bv[8];
            #pragma unroll
            for (int i = 0; i < 8; i++) a[i]  = As[kk][ty * 8 + i];
            #pragma unroll
            for (int j = 0; j < 8; j++) bv[j] = Bs[kk][tx * 8 + j];
            #pragma unroll
            for (int i = 0; i < 8; i++)
                #pragma unroll
                for (int j = 0; j < 8; j++)
                    acc[i][j] += a[i] * bv[j];
        }
        __syncthreads();
    }

    // Epilogue
    #pragma unroll
    for (int i = 0; i < 8; i++) {
        int r = brow + ty * 8 + i;
        #pragma unroll
        for (int j = 0; j < 8; j++) {
            int c = bcol + tx * 8 + j;
            float v = acc[i][j];
            if (EPI == 1) {
                v += bias[c];
                v = 0.5f * v * (1.0f + erff(v * 0.70710678118654752f));
            } else if (EPI == 2) {
                v += res[(size_t)r * N + c];
            } else if (EPI == 3) {
                v += bias[c] + res[(size_t)r * N + c];
            }
            C[(size_t)r * N + c] = v;
        }
    }
}

// ---------------------------------------------------------------------------
// Causal attention, fp32 flash-style.
// grid = (T/64, B*H), 256 threads. Each CTA: 64 q-rows for one (b,h).
// Online softmax, 4x4 register tiles on a 16x16 thread grid.
// Dynamic smem: Qs,Ks,Vs,Ps each [64][68] floats = 69632 B total.
// ---------------------------------------------------------------------------
#define APAD 68
#define ATTN_SMEM (4 * 64 * APAD * (int)sizeof(float))

__global__ __launch_bounds__(256) void attn_kernel(const float* __restrict__ qkv,
                                                   float* __restrict__ y)
{
    extern __shared__ float sm[];
    float (*Qs)[APAD] = (float(*)[APAD])(sm);
    float (*Ks)[APAD] = (float(*)[APAD])(sm + 1 * 64 * APAD);  // stored [d][c]
    float (*Vs)[APAD] = (float(*)[APAD])(sm + 2 * 64 * APAD);  // stored [j][d]
    float (*Ps)[APAD] = (float(*)[APAD])(sm + 3 * 64 * APAD);  // stored [r][j]

    int qb = blockIdx.x;             // q tile 0..15
    int bh = blockIdx.y;             // 0..23
    int b  = bh / HH, h = bh % HH;
    int tid = threadIdx.x;
    int ty = tid >> 4, tx = tid & 15;

    const float* base = qkv + (size_t)b * TT * D3 + h * HD;

    // Load Q tile [64 x 64]
    #pragma unroll
    for (int i = 0; i < 4; i++) {
        int s  = tid + i * 256;       // 0..1023
        int r  = s >> 4;              // 0..63
        int c4 = (s & 15) * 4;        // 0..60
        *(float4*)&Qs[r][c4] =
            *(const float4*)&base[(size_t)(qb * 64 + r) * D3 + c4];
    }

    float o[4][4];
    float m_run[4], l_run[4];
    #pragma unroll
    for (int i = 0; i < 4; i++) {
        m_run[i] = -INFINITY; l_run[i] = 0.0f;
        #pragma unroll
        for (int j = 0; j < 4; j++) o[i][j] = 0.0f;
    }
    const float scale = 0.125f;      // 1/sqrt(64)

    for (int kb = 0; kb <= qb; kb++) {
        __syncthreads();   // prior P@V done with Ks/Vs; Qs visible after next sync
        // K tile transposed -> Ks[d][c]; V tile natural -> Vs[j][d]
        #pragma unroll
        for (int i = 0; i < 4; i++) {
            int s  = tid + i * 256;
            int r  = s >> 4;
            int c4 = (s & 15) * 4;
            float4 kv = *(const float4*)&base[DD     + (size_t)(kb * 64 + r) * D3 + c4];
            Ks[c4 + 0][r] = kv.x; Ks[c4 + 1][r] = kv.y;
            Ks[c4 + 2][r] = kv.z; Ks[c4 + 3][r] = kv.w;
            *(float4*)&Vs[r][c4] =
                *(const float4*)&base[2 * DD + (size_t)(kb * 64 + r) * D3 + c4];
        }
        __syncthreads();

        // S = Q @ K^T  (4x4 per thread)
        float s4[4][4];
        #pragma unroll
        for (int i = 0; i < 4; i++)
            #pragma unroll
            for (int j = 0; j < 4; j++) s4[i][j] = 0.0f;
        #pragma unroll
        for (int d = 0; d < 64; d++) {
            float a[4], bv[4];
            #pragma unroll
            for (int i = 0; i < 4; i++) a[i]  = Qs[ty * 4 + i][d];
            #pragma unroll
            for (int j = 0; j < 4; j++) bv[j] = Ks[d][tx * 4 + j];
            #pragma unroll
            for (int i = 0; i < 4; i++)
                #pragma unroll
                for (int j = 0; j < 4; j++)
                    s4[i][j] += a[i] * bv[j];
        }

        bool diag = (kb == qb);
        #pragma unroll
        for (int i = 0; i < 4; i++)
            #pragma unroll
            for (int j = 0; j < 4; j++) {
                float v = s4[i][j] * scale;
                if (diag && (tx * 4 + j) > (ty * 4 + i)) v = -INFINITY;
                s4[i][j] = v;
            }

        // Online softmax update per row (16 tx-threads per 4-row group)
        #pragma unroll
        for (int i = 0; i < 4; i++) {
            float mx = fmaxf(fmaxf(s4[i][0], s4[i][1]), fmaxf(s4[i][2], s4[i][3]));
            #pragma unroll
            for (int off = 8; off >= 1; off >>= 1)
                mx = fmaxf(mx, __shfl_xor_sync(0xffffffffu, mx, off, 16));
            float nm    = fmaxf(m_run[i], mx);
            float alpha = expf(m_run[i] - nm);
            float rs = 0.0f;
            #pragma unroll
            for (int j = 0; j < 4; j++) {
                float p = expf(s4[i][j] - nm);
                s4[i][j] = p;
                rs += p;
            }
            #pragma unroll
            for (int off = 8; off >= 1; off >>= 1)
                rs += __shfl_xor_sync(0xffffffffu, rs, off, 16);
            l_run[i] = l_run[i] * alpha + rs;
            m_run[i] = nm;
            #pragma unroll
            for (int j = 0; j < 4; j++) o[i][j] *= alpha;
        }

        // Publish P, then O += P @ V
        #pragma unroll
        for (int i = 0; i < 4; i++)
            *(float4*)&Ps[ty * 4 + i][tx * 4] =
                make_float4(s4[i][0], s4[i][1], s4[i][2], s4[i][3]);
        __syncthreads();

        #pragma unroll
        for (int jj = 0; jj < 64; jj++) {
            float pv[4], vv[4];
            #pragma unroll
            for (int i = 0; i < 4; i++) pv[i] = Ps[ty * 4 + i][jj];
            #pragma unroll
            for (int j = 0; j < 4; j++) vv[j] = Vs[jj][tx * 4 + j];
            #pragma unroll
            for (int i = 0; i < 4; i++)
                #pragma unroll
                for (int j = 0; j < 4; j++)
                    o[i][j] += pv[i] * vv[j];
        }
    }

    // Normalize and store: y[b, t, h*64 + d]
    float* ybase = y + (size_t)b * TT * DD + h * HD;
    #pragma unroll
    for (int i = 0; i < 4; i++) {
        float inv = 1.0f / l_run[i];
        int r = qb * 64 + ty * 4 + i;
        #pragma unroll
        for (int j = 0; j < 4; j++)
            ybase[(size_t)r * DD + tx * 4 + j] = o[i][j] * inv;
    }
}

// ---------------------------------------------------------------------------
// Host orchestration
// ---------------------------------------------------------------------------
extern "C" void kernel_launch(void* const* d_in, const int* in_sizes, int n_in,
                              void* d_out, int out_size)
{
    (void)in_sizes; (void)n_in; (void)out_size;

    const int*   ids  = (const int*)  d_in[0];
    const float* tok  = (const float*)d_in[1];
    const float* pos  = (const float*)d_in[2];
    const float* ln1w = (const float*)d_in[3];
    const float* ln1b = (const float*)d_in[4];
    const float* qkvw = (const float*)d_in[5];
    const float* outw = (const float*)d_in[6];
    const float* ln2w = (const float*)d_in[7];
    const float* ln2b = (const float*)d_in[8];
    const float* w1   = (const float*)d_in[9];
    const float* b1   = (const float*)d_in[10];
    const float* w2   = (const float*)d_in[11];
    const float* b2   = (const float*)d_in[12];
    const float* lnfw = (const float*)d_in[13];
    const float* lnfb = (const float*)d_in[14];
    float* out = (float*)d_out;

    float *x, *h, *qkv, *y, *f1;
    cudaGetSymbolAddress((void**)&x,   g_x);
    cudaGetSymbolAddress((void**)&h,   g_h);
    cudaGetSymbolAddress((void**)&qkv, g_qkv);
    cudaGetSymbolAddress((void**)&y,   g_y);
    cudaGetSymbolAddress((void**)&f1,  g_f1);

    cudaFuncSetAttribute(attn_kernel,
                         cudaFuncAttributeMaxDynamicSharedMemorySize, ATTN_SMEM);

    // Embedding
    embed_kernel<<<(BT * DD) / 256, 256>>>(ids, tok, pos, x);

    for (int l = 0; l < LL; l++) {
        // LN1
        ln_kernel<<<BT, 256>>>(x, ln1w + l * DD, ln1b + l * DD, h);
        // QKV projection: [2048,768] @ [768,2304]
        sgemm<0, false><<<dim3(D3 / BN, BT / BM), 256>>>(
            h, qkvw + (size_t)l * DD * D3, nullptr, nullptr, qkv, BT, D3, DD);
        // Attention
        attn_kernel<<<dim3(TT / 64, BB * HH), 256, ATTN_SMEM>>>(qkv, y);
        // Out projection + residual (in-place on x)
        sgemm<2, false><<<dim3(DD / BN, BT / BM), 256>>>(
            y, outw + (size_t)l * DD * DD, nullptr, x, x, BT, DD, DD);
        // LN2
        ln_kernel<<<BT, 256>>>(x, ln2w + l * DD, ln2b + l * DD, h);
        // FFN1 + bias + exact GELU
        sgemm<1, false><<<dim3(FF / BN, BT / BM), 256>>>(
            h, w1 + (size_t)l * DD * FF, b1 + (size_t)l * FF, nullptr, f1, BT, FF, DD);
        // FFN2 + bias + residual (in-place on x)
        sgemm<3, false><<<dim3(DD / BN, BT / BM), 256>>>(
            f1, w2 + (size_t)l * FF * DD, b2 + (size_t)l * DD, x, x, BT, DD, FF);
    }

    // Final LN
    ln_kernel<<<BT, 256>>>(x, lnfw, lnfb, h);
    // Tied LM head: [2048,768] @ tok_emb[1024,768]^T
    sgemm<0, true><<<dim3(VV / BN, BT / BM), 256>>>(
        h, tok, nullptr, nullptr, out, BT, VV, DD);
}

// round 15
// speedup vs baseline: 1.9419x; 1.9390x over previous
#include <cuda_runtime.h>
#include <cuda_bf16.h>
#include <math.h>

// Problem constants
#define BB 2
#define TT 1024
#define DD 768
#define HH 12
#define HD 64
#define LL 8
#define FF 3072
#define VV 1024
#define BT (BB*TT)          // 2048
#define D3 (3*DD)           // 2304

// ---------------------------------------------------------------------------
// Scratch buffers (device globals; no allocation allowed)
// ---------------------------------------------------------------------------
__device__ float g_x  [BT * DD];   // residual stream
__device__ float g_h  [BT * DD];   // LN output / final-LN output
__device__ float g_qkv[BT * D3];   // qkv projection
__device__ float g_y  [BT * DD];   // attention output
__device__ float g_f1 [BT * FF];   // FFN hidden

// ---------------------------------------------------------------------------
// Embedding: x[b,t,:] = tok_emb[ids[b,t],:] + pos_emb[t,:]
// ---------------------------------------------------------------------------
__global__ void embed_kernel(const int* __restrict__ ids,
                             const float* __restrict__ tok,
                             const float* __restrict__ pos,
                             float* __restrict__ x)
{
    int idx = blockIdx.x * blockDim.x + threadIdx.x;   // < BT*DD
    int bt = idx / DD;
    int d  = idx - bt * DD;
    int t  = bt & (TT - 1);
    x[idx] = tok[(size_t)ids[bt] * DD + d] + pos[(size_t)t * DD + d];
}

// ---------------------------------------------------------------------------
// LayerNorm (two-pass, exact): one CTA per row, 256 threads, D=768
// ---------------------------------------------------------------------------
__global__ __launch_bounds__(256) void ln_kernel(const float* __restrict__ x,
                                                 const float* __restrict__ w,
                                                 const float* __restrict__ b,
                                                 float* __restrict__ out)
{
    int row = blockIdx.x;
    int tid = threadIdx.x;
    const float* xr = x + (size_t)row * DD;
    __shared__ float red[256];

    float v0 = xr[tid], v1 = xr[tid + 256], v2 = xr[tid + 512];

    red[tid] = v0 + v1 + v2;
    __syncthreads();
    #pragma unroll
    for (int off = 128; off > 0; off >>= 1) {
        if (tid < off) red[tid] += red[tid + off];
        __syncthreads();
    }
    float mu = red[0] * (1.0f / DD);
    __syncthreads();

    float d0 = v0 - mu, d1 = v1 - mu, d2 = v2 - mu;
    red[tid] = d0 * d0 + d1 * d1 + d2 * d2;
    __syncthreads();
    #pragma unroll
    for (int off = 128; off > 0; off >>= 1) {
        if (tid < off) red[tid] += red[tid + off];
        __syncthreads();
    }
    float rstd = rsqrtf(red[0] * (1.0f / DD) + 1e-5f);

    float* orow = out + (size_t)row * DD;
    orow[tid]       = d0 * rstd * w[tid]       + b[tid];
    orow[tid + 256] = d1 * rstd * w[tid + 256] + b[tid + 256];
    orow[tid + 512] = d2 * rstd * w[tid + 512] + b[tid + 512];
}

// ---------------------------------------------------------------------------
// TF32 tensor-core GEMM: C[M,N] = A[M,K] @ B  (B [K,N], or [N,K]^T if TB)
// 128x128 CTA tile, BK=32, 256 threads = 8 warps in 2(m) x 4(n) grid.
// Warp tile 64x32 -> 4x4 grid of m16n8k8 tf32 MMAs, fp32 accumulate.
// Smem k-major with pad 8 (row stride 136 -> quad groups hit banks 8t+g,
// conflict-free fragment loads).
// EPI: 0 = plain, 1 = +bias+exact GELU, 2 = +res, 3 = +bias+res
// ---------------------------------------------------------------------------
#define BM 128
#define BN 128
#define BK 32
#define SPAD 136   // BM + 8

__device__ __forceinline__ float f2tf32(float f) {
    unsigned r;
    asm("cvt.rna.tf32.f32 %0, %1;" : "=r"(r) : "f"(f));
    return __uint_as_float(r);
}

__device__ __forceinline__ void mma_tf32(float c[4], float a0, float a1,
                                         float a2, float a3,
                                         float b0, float b1) {
    asm volatile(
        "mma.sync.aligned.m16n8k8.row.col.f32.tf32.tf32.f32 "
        "{%0,%1,%2,%3}, {%4,%5,%6,%7}, {%8,%9}, {%0,%1,%2,%3};"
        : "+f"(c[0]), "+f"(c[1]), "+f"(c[2]), "+f"(c[3])
        : "r"(__float_as_uint(a0)), "r"(__float_as_uint(a1)),
          "r"(__float_as_uint(a2)), "r"(__float_as_uint(a3)),
          "r"(__float_as_uint(b0)), "r"(__float_as_uint(b1)));
}

template<int EPI, bool TB>
__global__ __launch_bounds__(256) void tgemm(const float* __restrict__ A,
                                             const float* __restrict__ Bm,
                                             const float* __restrict__ bias,
                                             const float* __restrict__ res,
                                             float* __restrict__ C,
                                             int M, int N, int K)
{
    __shared__ float As[BK][SPAD];   // [k][m]
    __shared__ float Bs[BK][SPAD];   // [k][n]

    int tid  = threadIdx.x;
    int brow = blockIdx.y * BM;
    int bcol = blockIdx.x * BN;

    int w   = tid >> 5;
    int l   = tid & 31;
    int wm  = w >> 2;            // 0..1
    int wn  = w & 3;             // 0..3
    int m0w = wm * 64;
    int n0w = wn * 32;
    int gid = l >> 2;            // 0..7
    int tig = l & 3;             // 0..3

    float acc[4][4][4];
    #pragma unroll
    for (int mt = 0; mt < 4; mt++)
        #pragma unroll
        for (int nt = 0; nt < 4; nt++)
            #pragma unroll
            for (int r = 0; r < 4; r++) acc[mt][nt][r] = 0.0f;

    for (int k0 = 0; k0 < K; k0 += BK) {
        // A tile [BM x BK] -> As[k][m], converted to tf32
        #pragma unroll
        for (int i = 0; i < 4; i++) {
            int s  = tid + i * 256;        // 0..1023
            int r  = s >> 3;               // 0..127
            int c4 = (s & 7) * 4;          // 0..28
            float4 v = *(const float4*)&A[(size_t)(brow + r) * K + k0 + c4];
            As[c4 + 0][r] = f2tf32(v.x); As[c4 + 1][r] = f2tf32(v.y);
            As[c4 + 2][r] = f2tf32(v.z); As[c4 + 3][r] = f2tf32(v.w);
        }
        // B tile -> Bs[k][n]
        if (!TB) {
            #pragma unroll
            for (int i = 0; i < 4; i++) {
                int s  = tid + i * 256;
                int r  = s >> 5;            // 0..31 (k)
                int c4 = (s & 31) * 4;      // 0..124 (n)
                float4 v = *(const float4*)&Bm[(size_t)(k0 + r) * N + bcol + c4];
                Bs[r][c4 + 0] = f2tf32(v.x); Bs[r][c4 + 1] = f2tf32(v.y);
                Bs[r][c4 + 2] = f2tf32(v.z); Bs[r][c4 + 3] = f2tf32(v.w);
            }
        } else {
            #pragma unroll
            for (int i = 0; i < 4; i++) {
                int s  = tid + i * 256;
                int r  = s >> 3;            // 0..127 (n)
                int c4 = (s & 7) * 4;       // 0..28  (k)
                float4 v = *(const float4*)&Bm[(size_t)(bcol + r) * K + k0 + c4];
                Bs[c4 + 0][r] = f2tf32(v.x); Bs[c4 + 1][r] = f2tf32(v.y);
                Bs[c4 + 2][r] = f2tf32(v.z); Bs[c4 + 3][r] = f2tf32(v.w);
            }
        }
        __syncthreads();

        #pragma unroll
        for (int kk = 0; kk < BK; kk += 8) {
            float a[4][4];
            #pragma unroll
            for (int mt = 0; mt < 4; mt++) {
                int m = m0w + mt * 16 + gid;
                a[mt][0] = As[kk + tig    ][m];
                a[mt][1] = As[kk + tig    ][m + 8];
                a[mt][2] = As[kk + tig + 4][m];
                a[mt][3] = As[kk + tig + 4][m + 8];
            }
            float bf[4][2];
            #pragma unroll
            for (int nt = 0; nt < 4; nt++) {
                int n = n0w + nt * 8 + gid;
                bf[nt][0] = Bs[kk + tig    ][n];
                bf[nt][1] = Bs[kk + tig + 4][n];
            }
            #pragma unroll
            for (int mt = 0; mt < 4; mt++)
                #pragma unroll
                for (int nt = 0; nt < 4; nt++)
                    mma_tf32(acc[mt][nt], a[mt][0], a[mt][1], a[mt][2], a[mt][3],
                             bf[nt][0], bf[nt][1]);
        }
        __syncthreads();
    }

    // Epilogue. c fragment: c0 (row gid, col 2*tig), c1 (+1), c2 (row gid+8), c3 (+1).
    #pragma unroll
    for (int mt = 0; mt < 4; mt++) {
        int r0 = brow + m0w + mt * 16 + gid;
        #pragma unroll
        for (int nt = 0; nt < 4; nt++) {
            int c = bcol + n0w + nt * 8 + 2 * tig;
            #pragma unroll
            for (int half = 0; half < 2; half++) {
                int rr = r0 + half * 8;
                float v0 = acc[mt][nt][half * 2 + 0];
                float v1 = acc[mt][nt][half * 2 + 1];
                if (EPI == 1) {
                    v0 += bias[c];
                    v1 += bias[c + 1];
                    v0 = 0.5f * v0 * (1.0f + erff(v0 * 0.70710678118654752f));
                    v1 = 0.5f * v1 * (1.0f + erff(v1 * 0.70710678118654752f));
                } else if (EPI == 2) {
                    v0 += res[(size_t)rr * N + c];
                    v1 += res[(size_t)rr * N + c + 1];
                } else if (EPI == 3) {
                    v0 += bias[c]     + res[(size_t)rr * N + c];
                    v1 += bias[c + 1] + res[(size_t)rr * N + c + 1];
                }
                *(float2*)&C[(size_t)rr * N + c] = make_float2(v0, v1);
            }
        }
    }
}

// ---------------------------------------------------------------------------
// Causal attention, fp32 flash-style (unchanged, exact fp32 path).
// grid = (T/64, B*H), 256 threads. Each CTA: 64 q-rows for one (b,h).
// ---------------------------------------------------------------------------
#define APAD 68
#define ATTN_SMEM (4 * 64 * APAD * (int)sizeof(float))

__global__ __launch_bounds__(256) void attn_kernel(const float* __restrict__ qkv,
                                                   float* __restrict__ y)
{
    extern __shared__ float sm[];
    float (*Qs)[APAD] = (float(*)[APAD])(sm);
    float (*Ks)[APAD] = (float(*)[APAD])(sm + 1 * 64 * APAD);  // stored [d][c]
    float (*Vs)[APAD] = (float(*)[APAD])(sm + 2 * 64 * APAD);  // stored [j][d]
    float (*Ps)[APAD] = (float(*)[APAD])(sm + 3 * 64 * APAD);  // stored [r][j]

    int qb = blockIdx.x;             // q tile 0..15
    int bh = blockIdx.y;             // 0..23
    int b  = bh / HH, h = bh % HH;
    int tid = threadIdx.x;
    int ty = tid >> 4, tx = tid & 15;

    const float* base = qkv + (size_t)b * TT * D3 + h * HD;

    // Load Q tile [64 x 64]
    #pragma unroll
    for (int i = 0; i < 4; i++) {
        int s  = tid + i * 256;       // 0..1023
        int r  = s >> 4;              // 0..63
        int c4 = (s & 15) * 4;        // 0..60
        *(float4*)&Qs[r][c4] =
            *(const float4*)&base[(size_t)(qb * 64 + r) * D3 + c4];
    }

    float o[4][4];
    float m_run[4], l_run[4];
    #pragma unroll
    for (int i = 0; i < 4; i++) {
        m_run[i] = -INFINITY; l_run[i] = 0.0f;
        #pragma unroll
        for (int j = 0; j < 4; j++) o[i][j] = 0.0f;
    }
    const float scale = 0.125f;      // 1/sqrt(64)

    for (int kb = 0; kb <= qb; kb++) {
        __syncthreads();
        #pragma unroll
        for (int i = 0; i < 4; i++) {
            int s  = tid + i * 256;
            int r  = s >> 4;
            int c4 = (s & 15) * 4;
            float4 kv = *(const float4*)&base[DD     + (size_t)(kb * 64 + r) * D3 + c4];
            Ks[c4 + 0][r] = kv.x; Ks[c4 + 1][r] = kv.y;
            Ks[c4 + 2][r] = kv.z; Ks[c4 + 3][r] = kv.w;
            *(float4*)&Vs[r][c4] =
                *(const float4*)&base[2 * DD + (size_t)(kb * 64 + r) * D3 + c4];
        }
        __syncthreads();

        float s4[4][4];
        #pragma unroll
        for (int i = 0; i < 4; i++)
            #pragma unroll
            for (int j = 0; j < 4; j++) s4[i][j] = 0.0f;
        #pragma unroll
        for (int d = 0; d < 64; d++) {
            float a[4], bv[4];
            #pragma unroll
            for (int i = 0; i < 4; i++) a[i]  = Qs[ty * 4 + i][d];
            #pragma unroll
            for (int j = 0; j < 4; j++) bv[j] = Ks[d][tx * 4 + j];
            #pragma unroll
            for (int i = 0; i < 4; i++)
                #pragma unroll
                for (int j = 0; j < 4; j++)
                    s4[i][j] += a[i] * bv[j];
        }

        bool diag = (kb == qb);
        #pragma unroll
        for (int i = 0; i < 4; i++)
            #pragma unroll
            for (int j = 0; j < 4; j++) {
                float v = s4[i][j] * scale;
                if (diag && (tx * 4 + j) > (ty * 4 + i)) v = -INFINITY;
                s4[i][j] = v;
            }

        #pragma unroll
        for (int i = 0; i < 4; i++) {
            float mx = fmaxf(fmaxf(s4[i][0], s4[i][1]), fmaxf(s4[i][2], s4[i][3]));
            #pragma unroll
            for (int off = 8; off >= 1; off >>= 1)
                mx = fmaxf(mx, __shfl_xor_sync(0xffffffffu, mx, off, 16));
            float nm    = fmaxf(m_run[i], mx);
            float alpha = expf(m_run[i] - nm);
            float rs = 0.0f;
            #pragma unroll
            for (int j = 0; j < 4; j++) {
                float p = expf(s4[i][j] - nm);
                s4[i][j] = p;
                rs += p;
            }
            #pragma unroll
            for (int off = 8; off >= 1; off >>= 1)
                rs += __shfl_xor_sync(0xffffffffu, rs, off, 16);
            l_run[i] = l_run[i] * alpha + rs;
            m_run[i] = nm;
            #pragma unroll
            for (int j = 0; j < 4; j++) o[i][j] *= alpha;
        }

        #pragma unroll
        for (int i = 0; i < 4; i++)
            *(float4*)&Ps[ty * 4 + i][tx * 4] =
                make_float4(s4[i][0], s4[i][1], s4[i][2], s4[i][3]);
        __syncthreads();

        #pragma unroll
        for (int jj = 0; jj < 64; jj++) {
            float pv[4], vv[4];
            #pragma unroll
            for (int i = 0; i < 4; i++) pv[i] = Ps[ty * 4 + i][jj];
            #pragma unroll
            for (int j = 0; j < 4; j++) vv[j] = Vs[jj][tx * 4 + j];
            #pragma unroll
            for (int i = 0; i < 4; i++)
                #pragma unroll
                for (int j = 0; j < 4; j++)
                    o[i][j] += pv[i] * vv[j];
        }
    }

    float* ybase = y + (size_t)b * TT * DD + h * HD;
    #pragma unroll
    for (int i = 0; i < 4; i++) {
        float inv = 1.0f / l_run[i];
        int r = qb * 64 + ty * 4 + i;
        #pragma unroll
        for (int j = 0; j < 4; j++)
            ybase[(size_t)r * DD + tx * 4 + j] = o[i][j] * inv;
    }
}

// ---------------------------------------------------------------------------
// Host orchestration
// ---------------------------------------------------------------------------
extern "C" void kernel_launch(void* const* d_in, const int* in_sizes, int n_in,
                              void* d_out, int out_size)
{
    (void)in_sizes; (void)n_in; (void)out_size;

    const int*   ids  = (const int*)  d_in[0];
    const float* tok  = (const float*)d_in[1];
    const float* pos  = (const float*)d_in[2];
    const float* ln1w = (const float*)d_in[3];
    const float* ln1b = (const float*)d_in[4];
    const float* qkvw = (const float*)d_in[5];
    const float* outw = (const float*)d_in[6];
    const float* ln2w = (const float*)d_in[7];
    const float* ln2b = (const float*)d_in[8];
    const float* w1   = (const float*)d_in[9];
    const float* b1   = (const float*)d_in[10];
    const float* w2   = (const float*)d_in[11];
    const float* b2   = (const float*)d_in[12];
    const float* lnfw = (const float*)d_in[13];
    const float* lnfb = (const float*)d_in[14];
    float* out = (float*)d_out;

    float *x, *h, *qkv, *y, *f1;
    cudaGetSymbolAddress((void**)&x,   g_x);
    cudaGetSymbolAddress((void**)&h,   g_h);
    cudaGetSymbolAddress((void**)&qkv, g_qkv);
    cudaGetSymbolAddress((void**)&y,   g_y);
    cudaGetSymbolAddress((void**)&f1,  g_f1);

    cudaFuncSetAttribute(attn_kernel,
                         cudaFuncAttributeMaxDynamicSharedMemorySize, ATTN_SMEM);

    // Embedding
    embed_kernel<<<(BT * DD) / 256, 256>>>(ids, tok, pos, x);

    for (int l = 0; l < LL; l++) {
        // LN1
        ln_kernel<<<BT, 256>>>(x, ln1w + l * DD, ln1b + l * DD, h);
        // QKV projection: [2048,768] @ [768,2304]
        tgemm<0, false><<<dim3(D3 / BN, BT / BM), 256>>>(
            h, qkvw + (size_t)l * DD * D3, nullptr, nullptr, qkv, BT, D3, DD);
        // Attention (exact fp32)
        attn_kernel<<<dim3(TT / 64, BB * HH), 256, ATTN_SMEM>>>(qkv, y);
        // Out projection + residual (in-place on x)
        tgemm<2, false><<<dim3(DD / BN, BT / BM), 256>>>(
            y, outw + (size_t)l * DD * DD, nullptr, x, x, BT, DD, DD);
        // LN2
        ln_kernel<<<BT, 256>>>(x, ln2w + l * DD, ln2b + l * DD, h);
        // FFN1 + bias + exact GELU
        tgemm<1, false><<<dim3(FF / BN, BT / BM), 256>>>(
            h, w1 + (size_t)l * DD * FF, b1 + (size_t)l * FF, nullptr, f1, BT, FF, DD);
        // FFN2 + bias + residual (in-place on x)
        tgemm<3, false><<<dim3(DD / BN, BT / BM), 256>>>(
            f1, w2 + (size_t)l * FF * DD, b2 + (size_t)l * DD, x, x, BT, DD, FF);
    }

    // Final LN
    ln_kernel<<<BT, 256>>>(x, lnfw, lnfb, h);
    // Tied LM head: [2048,768] @ tok_emb[1024,768]^T
    tgemm<0, true><<<dim3(VV / BN, BT / BM), 256>>>(
        h, tok, nullptr, nullptr, out, BT, VV, DD);
}

// round 16
// speedup vs baseline: 1.9425x; 1.0003x over previous
#include <cuda_runtime.h>
#include <cuda_bf16.h>
#include <math.h>

// Problem constants
#define BB 2
#define TT 1024
#define DD 768
#define HH 12
#define HD 64
#define LL 8
#define FF 3072
#define VV 1024
#define BT (BB*TT)          // 2048
#define D3 (3*DD)           // 2304

// ---------------------------------------------------------------------------
// Scratch buffers (device globals; no allocation allowed)
// ---------------------------------------------------------------------------
__device__ float g_x  [BT * DD];   // residual stream
__device__ float g_h  [BT * DD];   // LN output / final-LN output
__device__ float g_qkv[BT * D3];   // qkv projection
__device__ float g_y  [BT * DD];   // attention output
__device__ float g_f1 [BT * FF];   // FFN hidden

// ---------------------------------------------------------------------------
// Embedding: x[b,t,:] = tok_emb[ids[b,t],:] + pos_emb[t,:]
// ---------------------------------------------------------------------------
__global__ void embed_kernel(const int* __restrict__ ids,
                             const float* __restrict__ tok,
                             const float* __restrict__ pos,
                             float* __restrict__ x)
{
    int idx = blockIdx.x * blockDim.x + threadIdx.x;   // < BT*DD
    int bt = idx / DD;
    int d  = idx - bt * DD;
    int t  = bt & (TT - 1);
    x[idx] = tok[(size_t)ids[bt] * DD + d] + pos[(size_t)t * DD + d];
}

// ---------------------------------------------------------------------------
// LayerNorm (two-pass, exact): one CTA per row, 256 threads, D=768
// ---------------------------------------------------------------------------
__global__ __launch_bounds__(256) void ln_kernel(const float* __restrict__ x,
                                                 const float* __restrict__ w,
                                                 const float* __restrict__ b,
                                                 float* __restrict__ out)
{
    int row = blockIdx.x;
    int tid = threadIdx.x;
    const float* xr = x + (size_t)row * DD;
    __shared__ float red[256];

    float v0 = xr[tid], v1 = xr[tid + 256], v2 = xr[tid + 512];

    red[tid] = v0 + v1 + v2;
    __syncthreads();
    #pragma unroll
    for (int off = 128; off > 0; off >>= 1) {
        if (tid < off) red[tid] += red[tid + off];
        __syncthreads();
    }
    float mu = red[0] * (1.0f / DD);
    __syncthreads();

    float d0 = v0 - mu, d1 = v1 - mu, d2 = v2 - mu;
    red[tid] = d0 * d0 + d1 * d1 + d2 * d2;
    __syncthreads();
    #pragma unroll
    for (int off = 128; off > 0; off >>= 1) {
        if (tid < off) red[tid] += red[tid + off];
        __syncthreads();
    }
    float rstd = rsqrtf(red[0] * (1.0f / DD) + 1e-5f);

    float* orow = out + (size_t)row * DD;
    orow[tid]       = d0 * rstd * w[tid]       + b[tid];
    orow[tid + 256] = d1 * rstd * w[tid + 256] + b[tid + 256];
    orow[tid + 512] = d2 * rstd * w[tid + 512] + b[tid + 512];
}

// ---------------------------------------------------------------------------
// TF32 tensor-core GEMM: C[M,N] = A[M,K] @ B  (B [K,N], or [N,K]^T if TB)
// 128x128 CTA tile, BK=32, 256 threads = 8 warps in 2(m) x 4(n) grid.
// Warp tile 64x32 -> 4x4 grid of m16n8k8 tf32 MMAs, fp32 accumulate.
// Smem k-major with pad 8 (row stride 136 -> quad groups hit banks 8t+g,
// conflict-free fragment loads).
// EPI: 0 = plain, 1 = +bias+exact GELU, 2 = +res, 3 = +bias+res
// ---------------------------------------------------------------------------
#define BM 128
#define BN 128
#define BK 32
#define SPAD 136   // BM + 8

__device__ __forceinline__ float f2tf32(float f) {
    unsigned r;
    asm("cvt.rna.tf32.f32 %0, %1;" : "=r"(r) : "f"(f));
    return __uint_as_float(r);
}

__device__ __forceinline__ void mma_tf32(float c[4], float a0, float a1,
                                         float a2, float a3,
                                         float b0, float b1) {
    asm volatile(
        "mma.sync.aligned.m16n8k8.row.col.f32.tf32.tf32.f32 "
        "{%0,%1,%2,%3}, {%4,%5,%6,%7}, {%8,%9}, {%0,%1,%2,%3};"
        : "+f"(c[0]), "+f"(c[1]), "+f"(c[2]), "+f"(c[3])
        : "r"(__float_as_uint(a0)), "r"(__float_as_uint(a1)),
          "r"(__float_as_uint(a2)), "r"(__float_as_uint(a3)),
          "r"(__float_as_uint(b0)), "r"(__float_as_uint(b1)));
}

template<int EPI, bool TB>
__global__ __launch_bounds__(256) void tgemm(const float* __restrict__ A,
                                             const float* __restrict__ Bm,
                                             const float* __restrict__ bias,
                                             const float* __restrict__ res,
                                             float* __restrict__ C,
                                             int M, int N, int K)
{
    __shared__ float As[BK][SPAD];   // [k][m]
    __shared__ float Bs[BK][SPAD];   // [k][n]

    int tid  = threadIdx.x;
    int brow = blockIdx.y * BM;
    int bcol = blockIdx.x * BN;

    int w   = tid >> 5;
    int l   = tid & 31;
    int wm  = w >> 2;            // 0..1
    int wn  = w & 3;             // 0..3
    int m0w = wm * 64;
    int n0w = wn * 32;
    int gid = l >> 2;            // 0..7
    int tig = l & 3;             // 0..3

    float acc[4][4][4];
    #pragma unroll
    for (int mt = 0; mt < 4; mt++)
        #pragma unroll
        for (int nt = 0; nt < 4; nt++)
            #pragma unroll
            for (int r = 0; r < 4; r++) acc[mt][nt][r] = 0.0f;

    for (int k0 = 0; k0 < K; k0 += BK) {
        // A tile [BM x BK] -> As[k][m], converted to tf32
        #pragma unroll
        for (int i = 0; i < 4; i++) {
            int s  = tid + i * 256;        // 0..1023
            int r  = s >> 3;               // 0..127
            int c4 = (s & 7) * 4;          // 0..28
            float4 v = *(const float4*)&A[(size_t)(brow + r) * K + k0 + c4];
            As[c4 + 0][r] = f2tf32(v.x); As[c4 + 1][r] = f2tf32(v.y);
            As[c4 + 2][r] = f2tf32(v.z); As[c4 + 3][r] = f2tf32(v.w);
        }
        // B tile -> Bs[k][n]
        if (!TB) {
            #pragma unroll
            for (int i = 0; i < 4; i++) {
                int s  = tid + i * 256;
                int r  = s >> 5;            // 0..31 (k)
                int c4 = (s & 31) * 4;      // 0..124 (n)
                float4 v = *(const float4*)&Bm[(size_t)(k0 + r) * N + bcol + c4];
                Bs[r][c4 + 0] = f2tf32(v.x); Bs[r][c4 + 1] = f2tf32(v.y);
                Bs[r][c4 + 2] = f2tf32(v.z); Bs[r][c4 + 3] = f2tf32(v.w);
            }
        } else {
            #pragma unroll
            for (int i = 0; i < 4; i++) {
                int s  = tid + i * 256;
                int r  = s >> 3;            // 0..127 (n)
                int c4 = (s & 7) * 4;       // 0..28  (k)
                float4 v = *(const float4*)&Bm[(size_t)(bcol + r) * K + k0 + c4];
                Bs[c4 + 0][r] = f2tf32(v.x); Bs[c4 + 1][r] = f2tf32(v.y);
                Bs[c4 + 2][r] = f2tf32(v.z); Bs[c4 + 3][r] = f2tf32(v.w);
            }
        }
        __syncthreads();

        #pragma unroll
        for (int kk = 0; kk < BK; kk += 8) {
            float a[4][4];
            #pragma unroll
            for (int mt = 0; mt < 4; mt++) {
                int m = m0w + mt * 16 + gid;
                a[mt][0] = As[kk + tig    ][m];
                a[mt][1] = As[kk + tig    ][m + 8];
                a[mt][2] = As[kk + tig + 4][m];
                a[mt][3] = As[kk + tig + 4][m + 8];
            }
            float bf[4][2];
            #pragma unroll
            for (int nt = 0; nt < 4; nt++) {
                int n = n0w + nt * 8 + gid;
                bf[nt][0] = Bs[kk + tig    ][n];
                bf[nt][1] = Bs[kk + tig + 4][n];
            }
            #pragma unroll
            for (int mt = 0; mt < 4; mt++)
                #pragma unroll
                for (int nt = 0; nt < 4; nt++)
                    mma_tf32(acc[mt][nt], a[mt][0], a[mt][1], a[mt][2], a[mt][3],
                             bf[nt][0], bf[nt][1]);
        }
        __syncthreads();
    }

    // Epilogue. c fragment: c0 (row gid, col 2*tig), c1 (+1), c2 (row gid+8), c3 (+1).
    #pragma unroll
    for (int mt = 0; mt < 4; mt++) {
        int r0 = brow + m0w + mt * 16 + gid;
        #pragma unroll
        for (int nt = 0; nt < 4; nt++) {
            int c = bcol + n0w + nt * 8 + 2 * tig;
            #pragma unroll
            for (int half = 0; half < 2; half++) {
                int rr = r0 + half * 8;
                float v0 = acc[mt][nt][half * 2 + 0];
                float v1 = acc[mt][nt][half * 2 + 1];
                if (EPI == 1) {
                    v0 += bias[c];
                    v1 += bias[c + 1];
                    v0 = 0.5f * v0 * (1.0f + erff(v0 * 0.70710678118654752f));
                    v1 = 0.5f * v1 * (1.0f + erff(v1 * 0.70710678118654752f));
                } else if (EPI == 2) {
                    v0 += res[(size_t)rr * N + c];
                    v1 += res[(size_t)rr * N + c + 1];
                } else if (EPI == 3) {
                    v0 += bias[c]     + res[(size_t)rr * N + c];
                    v1 += bias[c + 1] + res[(size_t)rr * N + c + 1];
                }
                *(float2*)&C[(size_t)rr * N + c] = make_float2(v0, v1);
            }
        }
    }
}

// ---------------------------------------------------------------------------
// Causal attention, fp32 flash-style (unchanged, exact fp32 path).
// grid = (T/64, B*H), 256 threads. Each CTA: 64 q-rows for one (b,h).
// ---------------------------------------------------------------------------
#define APAD 68
#define ATTN_SMEM (4 * 64 * APAD * (int)sizeof(float))

__global__ __launch_bounds__(256) void attn_kernel(const float* __restrict__ qkv,
                                                   float* __restrict__ y)
{
    extern __shared__ float sm[];
    float (*Qs)[APAD] = (float(*)[APAD])(sm);
    float (*Ks)[APAD] = (float(*)[APAD])(sm + 1 * 64 * APAD);  // stored [d][c]
    float (*Vs)[APAD] = (float(*)[APAD])(sm + 2 * 64 * APAD);  // stored [j][d]
    float (*Ps)[APAD] = (float(*)[APAD])(sm + 3 * 64 * APAD);  // stored [r][j]

    int qb = blockIdx.x;             // q tile 0..15
    int bh = blockIdx.y;             // 0..23
    int b  = bh / HH, h = bh % HH;
    int tid = threadIdx.x;
    int ty = tid >> 4, tx = tid & 15;

    const float* base = qkv + (size_t)b * TT * D3 + h * HD;

    // Load Q tile [64 x 64]
    #pragma unroll
    for (int i = 0; i < 4; i++) {
        int s  = tid + i * 256;       // 0..1023
        int r  = s >> 4;              // 0..63
        int c4 = (s & 15) * 4;        // 0..60
        *(float4*)&Qs[r][c4] =
            *(const float4*)&base[(size_t)(qb * 64 + r) * D3 + c4];
    }

    float o[4][4];
    float m_run[4], l_run[4];
    #pragma unroll
    for (int i = 0; i < 4; i++) {
        m_run[i] = -INFINITY; l_run[i] = 0.0f;
        #pragma unroll
        for (int j = 0; j < 4; j++) o[i][j] = 0.0f;
    }
    const float scale = 0.125f;      // 1/sqrt(64)

    for (int kb = 0; kb <= qb; kb++) {
        __syncthreads();
        #pragma unroll
        for (int i = 0; i < 4; i++) {
            int s  = tid + i * 256;
            int r  = s >> 4;
            int c4 = (s & 15) * 4;
            float4 kv = *(const float4*)&base[DD     + (size_t)(kb * 64 + r) * D3 + c4];
            Ks[c4 + 0][r] = kv.x; Ks[c4 + 1][r] = kv.y;
            Ks[c4 + 2][r] = kv.z; Ks[c4 + 3][r] = kv.w;
            *(float4*)&Vs[r][c4] =
                *(const float4*)&base[2 * DD + (size_t)(kb * 64 + r) * D3 + c4];
        }
        __syncthreads();

        float s4[4][4];
        #pragma unroll
        for (int i = 0; i < 4; i++)
            #pragma unroll
            for (int j = 0; j < 4; j++) s4[i][j] = 0.0f;
        #pragma unroll
        for (int d = 0; d < 64; d++) {
            float a[4], bv[4];
            #pragma unroll
            for (int i = 0; i < 4; i++) a[i]  = Qs[ty * 4 + i][d];
            #pragma unroll
            for (int j = 0; j < 4; j++) bv[j] = Ks[d][tx * 4 + j];
            #pragma unroll
            for (int i = 0; i < 4; i++)
                #pragma unroll
                for (int j = 0; j < 4; j++)
                    s4[i][j] += a[i] * bv[j];
        }

        bool diag = (kb == qb);
        #pragma unroll
        for (int i = 0; i < 4; i++)
            #pragma unroll
            for (int j = 0; j < 4; j++) {
                float v = s4[i][j] * scale;
                if (diag && (tx * 4 + j) > (ty * 4 + i)) v = -INFINITY;
                s4[i][j] = v;
            }

        #pragma unroll
        for (int i = 0; i < 4; i++) {
            float mx = fmaxf(fmaxf(s4[i][0], s4[i][1]), fmaxf(s4[i][2], s4[i][3]));
            #pragma unroll
            for (int off = 8; off >= 1; off >>= 1)
                mx = fmaxf(mx, __shfl_xor_sync(0xffffffffu, mx, off, 16));
            float nm    = fmaxf(m_run[i], mx);
            float alpha = expf(m_run[i] - nm);
            float rs = 0.0f;
            #pragma unroll
            for (int j = 0; j < 4; j++) {
                float p = expf(s4[i][j] - nm);
                s4[i][j] = p;
                rs += p;
            }
            #pragma unroll
            for (int off = 8; off >= 1; off >>= 1)
                rs += __shfl_xor_sync(0xffffffffu, rs, off, 16);
            l_run[i] = l_run[i] * alpha + rs;
            m_run[i] = nm;
            #pragma unroll
            for (int j = 0; j < 4; j++) o[i][j] *= alpha;
        }

        #pragma unroll
        for (int i = 0; i < 4; i++)
            *(float4*)&Ps[ty * 4 + i][tx * 4] =
                make_float4(s4[i][0], s4[i][1], s4[i][2], s4[i][3]);
        __syncthreads();

        #pragma unroll
        for (int jj = 0; jj < 64; jj++) {
            float pv[4], vv[4];
            #pragma unroll
            for (int i = 0; i < 4; i++) pv[i] = Ps[ty * 4 + i][jj];
            #pragma unroll
            for (int j = 0; j < 4; j++) vv[j] = Vs[jj][tx * 4 + j];
            #pragma unroll
            for (int i = 0; i < 4; i++)
                #pragma unroll
                for (int j = 0; j < 4; j++)
                    o[i][j] += pv[i] * vv[j];
        }
    }

    float* ybase = y + (size_t)b * TT * DD + h * HD;
    #pragma unroll
    for (int i = 0; i < 4; i++) {
        float inv = 1.0f / l_run[i];
        int r = qb * 64 + ty * 4 + i;
        #pragma unroll
        for (int j = 0; j < 4; j++)
            ybase[(size_t)r * DD + tx * 4 + j] = o[i][j] * inv;
    }
}

// ---------------------------------------------------------------------------
// Host orchestration
// ---------------------------------------------------------------------------
extern "C" void kernel_launch(void* const* d_in, const int* in_sizes, int n_in,
                              void* d_out, int out_size)
{
    (void)in_sizes; (void)n_in; (void)out_size;

    const int*   ids  = (const int*)  d_in[0];
    const float* tok  = (const float*)d_in[1];
    const float* pos  = (const float*)d_in[2];
    const float* ln1w = (const float*)d_in[3];
    const float* ln1b = (const float*)d_in[4];
    const float* qkvw = (const float*)d_in[5];
    const float* outw = (const float*)d_in[6];
    const float* ln2w = (const float*)d_in[7];
    const float* ln2b = (const float*)d_in[8];
    const float* w1   = (const float*)d_in[9];
    const float* b1   = (const float*)d_in[10];
    const float* w2   = (const float*)d_in[11];
    const float* b2   = (const float*)d_in[12];
    const float* lnfw = (const float*)d_in[13];
    const float* lnfb = (const float*)d_in[14];
    float* out = (float*)d_out;

    float *x, *h, *qkv, *y, *f1;
    cudaGetSymbolAddress((void**)&x,   g_x);
    cudaGetSymbolAddress((void**)&h,   g_h);
    cudaGetSymbolAddress((void**)&qkv, g_qkv);
    cudaGetSymbolAddress((void**)&y,   g_y);
    cudaGetSymbolAddress((void**)&f1,  g_f1);

    cudaFuncSetAttribute(attn_kernel,
                         cudaFuncAttributeMaxDynamicSharedMemorySize, ATTN_SMEM);

    // Embedding
    embed_kernel<<<(BT * DD) / 256, 256>>>(ids, tok, pos, x);

    for (int l = 0; l < LL; l++) {
        // LN1
        ln_kernel<<<BT, 256>>>(x, ln1w + l * DD, ln1b + l * DD, h);
        // QKV projection: [2048,768] @ [768,2304]
        tgemm<0, false><<<dim3(D3 / BN, BT / BM), 256>>>(
            h, qkvw + (size_t)l * DD * D3, nullptr, nullptr, qkv, BT, D3, DD);
        // Attention (exact fp32)
        attn_kernel<<<dim3(TT / 64, BB * HH), 256, ATTN_SMEM>>>(qkv, y);
        // Out projection + residual (in-place on x)
        tgemm<2, false><<<dim3(DD / BN, BT / BM), 256>>>(
            y, outw + (size_t)l * DD * DD, nullptr, x, x, BT, DD, DD);
        // LN2
        ln_kernel<<<BT, 256>>>(x, ln2w + l * DD, ln2b + l * DD, h);
        // FFN1 + bias + exact GELU
        tgemm<1, false><<<dim3(FF / BN, BT / BM), 256>>>(
            h, w1 + (size_t)l * DD * FF, b1 + (size_t)l * FF, nullptr, f1, BT, FF, DD);
        // FFN2 + bias + residual (in-place on x)
        tgemm<3, false><<<dim3(DD / BN, BT / BM), 256>>>(
            f1, w2 + (size_t)l * FF * DD, b2 + (size_t)l * DD, x, x, BT, DD, FF);
    }

    // Final LN
    ln_kernel<<<BT, 256>>>(x, lnfw, lnfb, h);
    // Tied LM head: [2048,768] @ tok_emb[1024,768]^T
    tgemm<0, true><<<dim3(VV / BN, BT / BM), 256>>>(
        h, tok, nullptr, nullptr, out, BT, VV, DD);
}

// round 17
// speedup vs baseline: 2.0400x; 1.0502x over previous
#include <cuda_runtime.h>
#include <cuda_bf16.h>
#include <math.h>

// Problem constants
#define BB 2
#define TT 1024
#define DD 768
#define HH 12
#define HD 64
#define LL 8
#define FF 3072
#define VV 1024
#define BT (BB*TT)          // 2048
#define D3 (3*DD)           // 2304

// ---------------------------------------------------------------------------
// Scratch buffers (device globals; no allocation allowed)
// ---------------------------------------------------------------------------
__device__ float g_x  [BT * DD];
__device__ float g_h  [BT * DD];
__device__ float g_qkv[BT * D3];
__device__ float g_y  [BT * DD];
__device__ float g_f1 [BT * FF];

// ---------------------------------------------------------------------------
// Small helpers
// ---------------------------------------------------------------------------
__device__ __forceinline__ float f2tf32(float f) {
    unsigned r;
    asm("cvt.rna.tf32.f32 %0, %1;" : "=r"(r) : "f"(f));
    return __uint_as_float(r);
}

__device__ __forceinline__ void mma_tf32(float c[4], float a0, float a1,
                                         float a2, float a3,
                                         float b0, float b1) {
    asm volatile(
        "mma.sync.aligned.m16n8k8.row.col.f32.tf32.tf32.f32 "
        "{%0,%1,%2,%3}, {%4,%5,%6,%7}, {%8,%9}, {%0,%1,%2,%3};"
        : "+f"(c[0]), "+f"(c[1]), "+f"(c[2]), "+f"(c[3])
        : "r"(__float_as_uint(a0)), "r"(__float_as_uint(a1)),
          "r"(__float_as_uint(a2)), "r"(__float_as_uint(a3)),
          "r"(__float_as_uint(b0)), "r"(__float_as_uint(b1)));
}

__device__ __forceinline__ void cp16(void* dst_smem, const void* src) {
    unsigned d = (unsigned)__cvta_generic_to_shared(dst_smem);
    asm volatile("cp.async.ca.shared.global [%0], [%1], 16;" :: "r"(d), "l"(src));
}
__device__ __forceinline__ void cp_commit() {
    asm volatile("cp.async.commit_group;");
}
__device__ __forceinline__ void cp_wait0() {
    asm volatile("cp.async.wait_group 0;");
}

// ---------------------------------------------------------------------------
// Embedding
// ---------------------------------------------------------------------------
__global__ void embed_kernel(const int* __restrict__ ids,
                             const float* __restrict__ tok,
                             const float* __restrict__ pos,
                             float* __restrict__ x)
{
    int idx = blockIdx.x * blockDim.x + threadIdx.x;
    int bt = idx / DD;
    int d  = idx - bt * DD;
    int t  = bt & (TT - 1);
    x[idx] = tok[(size_t)ids[bt] * DD + d] + pos[(size_t)t * DD + d];
}

// ---------------------------------------------------------------------------
// LayerNorm: shuffle reduction, 3 barriers total.
// ---------------------------------------------------------------------------
__global__ __launch_bounds__(256) void ln_kernel(const float* __restrict__ x,
                                                 const float* __restrict__ w,
                                                 const float* __restrict__ b,
                                                 float* __restrict__ out)
{
    int row = blockIdx.x;
    int tid = threadIdx.x;
    int lane = tid & 31, wid = tid >> 5;
    const float* xr = x + (size_t)row * DD;
    __shared__ float part[8];

    float v0 = xr[tid], v1 = xr[tid + 256], v2 = xr[tid + 512];

    float s = v0 + v1 + v2;
    #pragma unroll
    for (int off = 16; off >= 1; off >>= 1)
        s += __shfl_xor_sync(0xffffffffu, s, off);
    if (lane == 0) part[wid] = s;
    __syncthreads();
    float tot = part[0] + part[1] + part[2] + part[3]
              + part[4] + part[5] + part[6] + part[7];
    float mu = tot * (1.0f / DD);

    float d0 = v0 - mu, d1 = v1 - mu, d2 = v2 - mu;
    float q = d0 * d0 + d1 * d1 + d2 * d2;
    #pragma unroll
    for (int off = 16; off >= 1; off >>= 1)
        q += __shfl_xor_sync(0xffffffffu, q, off);
    __syncthreads();                    // everyone done reading part[]
    if (lane == 0) part[wid] = q;
    __syncthreads();
    float var = (part[0] + part[1] + part[2] + part[3]
               + part[4] + part[5] + part[6] + part[7]) * (1.0f / DD);
    float rstd = rsqrtf(var + 1e-5f);

    float* orow = out + (size_t)row * DD;
    orow[tid]       = d0 * rstd * w[tid]       + b[tid];
    orow[tid + 256] = d1 * rstd * w[tid + 256] + b[tid + 256];
    orow[tid + 512] = d2 * rstd * w[tid + 512] + b[tid + 512];
}

// ---------------------------------------------------------------------------
// Pipelined TF32 GEMM (non-transposed B): C[M,N] = A[M,K] @ B[K,N]
// 128x128 CTA tile, BK=32, cp.async double-buffered smem, 1 sync per iter.
// A smem [m][k] stride 36 (banks 4*gid+tig: conflict-free fragment loads)
// B smem [k][n] stride 136 (banks 8*tig+gid: conflict-free)
// RNA tf32 convert at fragment-load time.
// EPI: 0 plain, 1 +bias+GELU, 2 +res, 3 +bias+res
// ---------------------------------------------------------------------------
#define PBM 128
#define PBN 128
#define PBK 32
#define ASTR 36      // PBK + 4 floats
#define BSTR 136     // PBN + 8 floats
#define AELT (PBM * ASTR)            // 4608 floats
#define BELT (PBK * BSTR)            // 4352 floats
#define BUFELT (AELT + BELT)         // 8960 floats
#define PIPE_SMEM (2 * BUFELT * (int)sizeof(float))   // 71680 B

template<int EPI>
__global__ __launch_bounds__(256, 2) void tgemm_pipe(const float* __restrict__ A,
                                                     const float* __restrict__ Bm,
                                                     const float* __restrict__ bias,
                                                     const float* __restrict__ res,
                                                     float* __restrict__ C,
                                                     int M, int N, int K)
{
    extern __shared__ float smp[];

    int tid  = threadIdx.x;
    int brow = blockIdx.y * PBM;
    int bcol = blockIdx.x * PBN;

    int w   = tid >> 5;
    int l   = tid & 31;
    int wm  = w >> 2;
    int wn  = w & 3;
    int m0w = wm * 64;
    int n0w = wn * 32;
    int gid = l >> 2;
    int tig = l & 3;

    // Per-thread cp.async offsets
    int ar  = tid >> 1;                // 0..127  (A row, 2 chunks each)
    int ac  = (tid & 1) * 16;          // 0 or 16 (k offset; 2x16 floats = 32)
    int br_ = tid >> 3;                // 0..31   (B k-row, 4 chunks each)
    int bc_ = (tid & 7) * 16;          // 0..112  (n offset; first of 4 strided)

    const float* Asrc = A + (size_t)(brow + ar) * K + ac;
    const float* Bsrc = Bm + (size_t)br_ * N + bcol + bc_;

    float acc[4][4][4];
    #pragma unroll
    for (int mt = 0; mt < 4; mt++)
        #pragma unroll
        for (int nt = 0; nt < 4; nt++)
            #pragma unroll
            for (int r = 0; r < 4; r++) acc[mt][nt][r] = 0.0f;

    int nk = K / PBK;

    // Prologue: fill buffer 0
    {
        float* As = smp;
        float* Bs = smp + AELT;
        cp16(&As[ar * ASTR + ac],      Asrc);
        cp16(&As[ar * ASTR + ac + 4],  Asrc + 4);
        cp16(&As[ar * ASTR + ac + 8],  Asrc + 8);
        cp16(&As[ar * ASTR + ac + 12], Asrc + 12);
        #pragma unroll
        for (int i = 0; i < 4; i++)
            cp16(&Bs[br_ * BSTR + bc_ + i * 4], Bsrc + i * 4);
        cp_commit();
    }

    for (int kb = 0; kb < nk; kb++) {
        int cur = kb & 1;
        cp_wait0();
        __syncthreads();

        if (kb + 1 < nk) {
            float* As = smp + (1 - cur) * BUFELT;
            float* Bs = As + AELT;
            const float* as = Asrc + (kb + 1) * PBK;
            const float* bs = Bsrc + (size_t)(kb + 1) * PBK * N;
            cp16(&As[ar * ASTR + ac],      as);
            cp16(&As[ar * ASTR + ac + 4],  as + 4);
            cp16(&As[ar * ASTR + ac + 8],  as + 8);
            cp16(&As[ar * ASTR + ac + 12], as + 12);
            #pragma unroll
            for (int i = 0; i < 4; i++)
                cp16(&Bs[br_ * BSTR + bc_ + i * 4], bs + i * 4);
            cp_commit();
        }

        const float* As = smp + cur * BUFELT;
        const float* Bs = As + AELT;

        #pragma unroll
        for (int kk = 0; kk < PBK; kk += 8) {
            float a[4][4];
            #pragma unroll
            for (int mt = 0; mt < 4; mt++) {
                int m = m0w + mt * 16 + gid;
                a[mt][0] = f2tf32(As[(m    ) * ASTR + kk + tig    ]);
                a[mt][1] = f2tf32(As[(m + 8) * ASTR + kk + tig    ]);
                a[mt][2] = f2tf32(As[(m    ) * ASTR + kk + tig + 4]);
                a[mt][3] = f2tf32(As[(m + 8) * ASTR + kk + tig + 4]);
            }
            float bf[4][2];
            #pragma unroll
            for (int nt = 0; nt < 4; nt++) {
                int n = n0w + nt * 8 + gid;
                bf[nt][0] = f2tf32(Bs[(kk + tig    ) * BSTR + n]);
                bf[nt][1] = f2tf32(Bs[(kk + tig + 4) * BSTR + n]);
            }
            #pragma unroll
            for (int mt = 0; mt < 4; mt++)
                #pragma unroll
                for (int nt = 0; nt < 4; nt++)
                    mma_tf32(acc[mt][nt], a[mt][0], a[mt][1], a[mt][2], a[mt][3],
                             bf[nt][0], bf[nt][1]);
        }
    }

    // Epilogue
    #pragma unroll
    for (int mt = 0; mt < 4; mt++) {
        int r0 = brow + m0w + mt * 16 + gid;
        #pragma unroll
        for (int nt = 0; nt < 4; nt++) {
            int c = bcol + n0w + nt * 8 + 2 * tig;
            #pragma unroll
            for (int half = 0; half < 2; half++) {
                int rr = r0 + half * 8;
                float v0 = acc[mt][nt][half * 2 + 0];
                float v1 = acc[mt][nt][half * 2 + 1];
                if (EPI == 1) {
                    v0 += bias[c];
                    v1 += bias[c + 1];
                    v0 = 0.5f * v0 * (1.0f + erff(v0 * 0.70710678118654752f));
                    v1 = 0.5f * v1 * (1.0f + erff(v1 * 0.70710678118654752f));
                } else if (EPI == 2) {
                    v0 += res[(size_t)rr * N + c];
                    v1 += res[(size_t)rr * N + c + 1];
                } else if (EPI == 3) {
                    v0 += bias[c]     + res[(size_t)rr * N + c];
                    v1 += bias[c + 1] + res[(size_t)rr * N + c + 1];
                }
                *(float2*)&C[(size_t)rr * N + c] = make_float2(v0, v1);
            }
        }
    }
}

// ---------------------------------------------------------------------------
// 3-term split-TF32 GEMM (near-fp32 exact), transposed B. Used for lm_head.
// C[M,N] = A[M,K] @ B[N,K]^T. Original synchronous structure; raw fp32 smem,
// hi/lo split at fragment load, 3 MMAs per tile.
// ---------------------------------------------------------------------------
#define BM 128
#define BN 128
#define BK 32
#define SPAD 136

__global__ __launch_bounds__(256) void tgemm_split_tb(const float* __restrict__ A,
                                                      const float* __restrict__ Bm,
                                                      float* __restrict__ C,
                                                      int M, int N, int K)
{
    __shared__ float As[BK][SPAD];   // [k][m], raw fp32
    __shared__ float Bs[BK][SPAD];   // [k][n], raw fp32

    int tid  = threadIdx.x;
    int brow = blockIdx.y * BM;
    int bcol = blockIdx.x * BN;

    int w   = tid >> 5;
    int l   = tid & 31;
    int wm  = w >> 2;
    int wn  = w & 3;
    int m0w = wm * 64;
    int n0w = wn * 32;
    int gid = l >> 2;
    int tig = l & 3;

    float acc[4][4][4];
    #pragma unroll
    for (int mt = 0; mt < 4; mt++)
        #pragma unroll
        for (int nt = 0; nt < 4; nt++)
            #pragma unroll
            for (int r = 0; r < 4; r++) acc[mt][nt][r] = 0.0f;

    for (int k0 = 0; k0 < K; k0 += BK) {
        #pragma unroll
        for (int i = 0; i < 4; i++) {
            int s  = tid + i * 256;
            int r  = s >> 3;
            int c4 = (s & 7) * 4;
            float4 v = *(const float4*)&A[(size_t)(brow + r) * K + k0 + c4];
            As[c4 + 0][r] = v.x; As[c4 + 1][r] = v.y;
            As[c4 + 2][r] = v.z; As[c4 + 3][r] = v.w;
            float4 u = *(const float4*)&Bm[(size_t)(bcol + r) * K + k0 + c4];
            Bs[c4 + 0][r] = u.x; Bs[c4 + 1][r] = u.y;
            Bs[c4 + 2][r] = u.z; Bs[c4 + 3][r] = u.w;
        }
        __syncthreads();

        #pragma unroll
        for (int kk = 0; kk < BK; kk += 8) {
            float ah[4][4], al[4][4];
            #pragma unroll
            for (int mt = 0; mt < 4; mt++) {
                int m = m0w + mt * 16 + gid;
                float r0 = As[kk + tig    ][m];
                float r1 = As[kk + tig    ][m + 8];
                float r2 = As[kk + tig + 4][m];
                float r3 = As[kk + tig + 4][m + 8];
                ah[mt][0] = f2tf32(r0); al[mt][0] = f2tf32(r0 - ah[mt][0]);
                ah[mt][1] = f2tf32(r1); al[mt][1] = f2tf32(r1 - ah[mt][1]);
                ah[mt][2] = f2tf32(r2); al[mt][2] = f2tf32(r2 - ah[mt][2]);
                ah[mt][3] = f2tf32(r3); al[mt][3] = f2tf32(r3 - ah[mt][3]);
            }
            float bh[4][2], bl[4][2];
            #pragma unroll
            for (int nt = 0; nt < 4; nt++) {
                int n = n0w + nt * 8 + gid;
                float r0 = Bs[kk + tig    ][n];
                float r1 = Bs[kk + tig + 4][n];
                bh[nt][0] = f2tf32(r0); bl[nt][0] = f2tf32(r0 - bh[nt][0]);
                bh[nt][1] = f2tf32(r1); bl[nt][1] = f2tf32(r1 - bh[nt][1]);
            }
            #pragma unroll
            for (int mt = 0; mt < 4; mt++)
                #pragma unroll
                for (int nt = 0; nt < 4; nt++) {
                    mma_tf32(acc[mt][nt], al[mt][0], al[mt][1], al[mt][2], al[mt][3],
                             bh[nt][0], bh[nt][1]);
                    mma_tf32(acc[mt][nt], ah[mt][0], ah[mt][1], ah[mt][2], ah[mt][3],
                             bl[nt][0], bl[nt][1]);
                    mma_tf32(acc[mt][nt], ah[mt][0], ah[mt][1], ah[mt][2], ah[mt][3],
                             bh[nt][0], bh[nt][1]);
                }
        }
        __syncthreads();
    }

    #pragma unroll
    for (int mt = 0; mt < 4; mt++) {
        int r0 = brow + m0w + mt * 16 + gid;
        #pragma unroll
        for (int nt = 0; nt < 4; nt++) {
            int c = bcol + n0w + nt * 8 + 2 * tig;
            #pragma unroll
            for (int half = 0; half < 2; half++) {
                int rr = r0 + half * 8;
                *(float2*)&C[(size_t)rr * N + c] =
                    make_float2(acc[mt][nt][half * 2 + 0], acc[mt][nt][half * 2 + 1]);
            }
        }
    }
}

// ---------------------------------------------------------------------------
// Causal attention, exact fp32 flash-style, float4-vectorized smem loads.
// grid = (T/64, B*H), 256 threads. Heavy tiles scheduled first.
// ---------------------------------------------------------------------------
#define APAD 68
#define ATTN_SMEM (4 * 64 * APAD * (int)sizeof(float))

__global__ __launch_bounds__(256) void attn_kernel(const float* __restrict__ qkv,
                                                   float* __restrict__ y)
{
    extern __shared__ float sm[];
    float (*Qs)[APAD] = (float(*)[APAD])(sm);
    float (*Ks)[APAD] = (float(*)[APAD])(sm + 1 * 64 * APAD);  // [d][c]
    float (*Vs)[APAD] = (float(*)[APAD])(sm + 2 * 64 * APAD);  // [j][d]
    float (*Ps)[APAD] = (float(*)[APAD])(sm + 3 * 64 * APAD);  // [r][j]

    int qb = (gridDim.x - 1) - blockIdx.x;   // heavy tiles first
    int bh = blockIdx.y;
    int b  = bh / HH, h = bh % HH;
    int tid = threadIdx.x;
    int ty = tid >> 4, tx = tid & 15;

    const float* base = qkv + (size_t)b * TT * D3 + h * HD;

    #pragma unroll
    for (int i = 0; i < 4; i++) {
        int s  = tid + i * 256;
        int r  = s >> 4;
        int c4 = (s & 15) * 4;
        *(float4*)&Qs[r][c4] =
            *(const float4*)&base[(size_t)(qb * 64 + r) * D3 + c4];
    }

    float o[4][4];
    float m_run[4], l_run[4];
    #pragma unroll
    for (int i = 0; i < 4; i++) {
        m_run[i] = -INFINITY; l_run[i] = 0.0f;
        #pragma unroll
        for (int j = 0; j < 4; j++) o[i][j] = 0.0f;
    }
    const float scale = 0.125f;

    for (int kb = 0; kb <= qb; kb++) {
        __syncthreads();
        #pragma unroll
        for (int i = 0; i < 4; i++) {
            int s  = tid + i * 256;
            int r  = s >> 4;
            int c4 = (s & 15) * 4;
            float4 kv = *(const float4*)&base[DD     + (size_t)(kb * 64 + r) * D3 + c4];
            Ks[c4 + 0][r] = kv.x; Ks[c4 + 1][r] = kv.y;
            Ks[c4 + 2][r] = kv.z; Ks[c4 + 3][r] = kv.w;
            *(float4*)&Vs[r][c4] =
                *(const float4*)&base[2 * DD + (size_t)(kb * 64 + r) * D3 + c4];
        }
        __syncthreads();

        // S = Q @ K^T, float4-vectorized over d
        float s4[4][4];
        #pragma unroll
        for (int i = 0; i < 4; i++)
            #pragma unroll
            for (int j = 0; j < 4; j++) s4[i][j] = 0.0f;

        #pragma unroll
        for (int d0 = 0; d0 < 64; d0 += 4) {
            float a[4][4], bv[4][4];
            #pragma unroll
            for (int i = 0; i < 4; i++)
                *(float4*)&a[i][0] = *(const float4*)&Qs[ty * 4 + i][d0];
            #pragma unroll
            for (int dd = 0; dd < 4; dd++)
                *(float4*)&bv[dd][0] = *(const float4*)&Ks[d0 + dd][tx * 4];
            #pragma unroll
            for (int dd = 0; dd < 4; dd++)
                #pragma unroll
                for (int i = 0; i < 4; i++)
                    #pragma unroll
                    for (int j = 0; j < 4; j++)
                        s4[i][j] += a[i][dd] * bv[dd][j];
        }

        bool diag = (kb == qb);
        #pragma unroll
        for (int i = 0; i < 4; i++)
            #pragma unroll
            for (int j = 0; j < 4; j++) {
                float v = s4[i][j] * scale;
                if (diag && (tx * 4 + j) > (ty * 4 + i)) v = -INFINITY;
                s4[i][j] = v;
            }

        #pragma unroll
        for (int i = 0; i < 4; i++) {
            float mx = fmaxf(fmaxf(s4[i][0], s4[i][1]), fmaxf(s4[i][2], s4[i][3]));
            #pragma unroll
            for (int off = 8; off >= 1; off >>= 1)
                mx = fmaxf(mx, __shfl_xor_sync(0xffffffffu, mx, off, 16));
            float nm    = fmaxf(m_run[i], mx);
            float alpha = expf(m_run[i] - nm);
            float rs = 0.0f;
            #pragma unroll
            for (int j = 0; j < 4; j++) {
                float p = expf(s4[i][j] - nm);
                s4[i][j] = p;
                rs += p;
            }
            #pragma unroll
            for (int off = 8; off >= 1; off >>= 1)
                rs += __shfl_xor_sync(0xffffffffu, rs, off, 16);
            l_run[i] = l_run[i] * alpha + rs;
            m_run[i] = nm;
            #pragma unroll
            for (int j = 0; j < 4; j++) o[i][j] *= alpha;
        }

        #pragma unroll
        for (int i = 0; i < 4; i++)
            *(float4*)&Ps[ty * 4 + i][tx * 4] =
                make_float4(s4[i][0], s4[i][1], s4[i][2], s4[i][3]);
        __syncthreads();

        // O += P @ V, float4-vectorized over jj
        #pragma unroll
        for (int jj0 = 0; jj0 < 64; jj0 += 4) {
            float pv[4][4], vv[4][4];
            #pragma unroll
            for (int i = 0; i < 4; i++)
                *(float4*)&pv[i][0] = *(const float4*)&Ps[ty * 4 + i][jj0];
            #pragma unroll
            for (int dd = 0; dd < 4; dd++)
                *(float4*)&vv[dd][0] = *(const float4*)&Vs[jj0 + dd][tx * 4];
            #pragma unroll
            for (int dd = 0; dd < 4; dd++)
                #pragma unroll
                for (int i = 0; i < 4; i++)
                    #pragma unroll
                    for (int j = 0; j < 4; j++)
                        o[i][j] += pv[i][dd] * vv[dd][j];
        }
    }

    float* ybase = y + (size_t)b * TT * DD + h * HD;
    #pragma unroll
    for (int i = 0; i < 4; i++) {
        float inv = 1.0f / l_run[i];
        int r = qb * 64 + ty * 4 + i;
        #pragma unroll
        for (int j = 0; j < 4; j++)
            ybase[(size_t)r * DD + tx * 4 + j] = o[i][j] * inv;
    }
}

// ---------------------------------------------------------------------------
// Host orchestration
// ---------------------------------------------------------------------------
extern "C" void kernel_launch(void* const* d_in, const int* in_sizes, int n_in,
                              void* d_out, int out_size)
{
    (void)in_sizes; (void)n_in; (void)out_size;

    const int*   ids  = (const int*)  d_in[0];
    const float* tok  = (const float*)d_in[1];
    const float* pos  = (const float*)d_in[2];
    const float* ln1w = (const float*)d_in[3];
    const float* ln1b = (const float*)d_in[4];
    const float* qkvw = (const float*)d_in[5];
    const float* outw = (const float*)d_in[6];
    const float* ln2w = (const float*)d_in[7];
    const float* ln2b = (const float*)d_in[8];
    const float* w1   = (const float*)d_in[9];
    const float* b1   = (const float*)d_in[10];
    const float* w2   = (const float*)d_in[11];
    const float* b2   = (const float*)d_in[12];
    const float* lnfw = (const float*)d_in[13];
    const float* lnfb = (const float*)d_in[14];
    float* out = (float*)d_out;

    float *x, *h, *qkv, *y, *f1;
    cudaGetSymbolAddress((void**)&x,   g_x);
    cudaGetSymbolAddress((void**)&h,   g_h);
    cudaGetSymbolAddress((void**)&qkv, g_qkv);
    cudaGetSymbolAddress((void**)&y,   g_y);
    cudaGetSymbolAddress((void**)&f1,  g_f1);

    cudaFuncSetAttribute(attn_kernel,
                         cudaFuncAttributeMaxDynamicSharedMemorySize, ATTN_SMEM);
    cudaFuncSetAttribute(tgemm_pipe<0>,
                         cudaFuncAttributeMaxDynamicSharedMemorySize, PIPE_SMEM);
    cudaFuncSetAttribute(tgemm_pipe<1>,
                         cudaFuncAttributeMaxDynamicSharedMemorySize, PIPE_SMEM);
    cudaFuncSetAttribute(tgemm_pipe<2>,
                         cudaFuncAttributeMaxDynamicSharedMemorySize, PIPE_SMEM);
    cudaFuncSetAttribute(tgemm_pipe<3>,
                         cudaFuncAttributeMaxDynamicSharedMemorySize, PIPE_SMEM);

    // Embedding
    embed_kernel<<<(BT * DD) / 256, 256>>>(ids, tok, pos, x);

    for (int l = 0; l < LL; l++) {
        // LN1
        ln_kernel<<<BT, 256>>>(x, ln1w + l * DD, ln1b + l * DD, h);
        // QKV projection: [2048,768] @ [768,2304]
        tgemm_pipe<0><<<dim3(D3 / PBN, BT / PBM), 256, PIPE_SMEM>>>(
            h, qkvw + (size_t)l * DD * D3, nullptr, nullptr, qkv, BT, D3, DD);
        // Attention (exact fp32)
        attn_kernel<<<dim3(TT / 64, BB * HH), 256, ATTN_SMEM>>>(qkv, y);
        // Out projection + residual (in-place on x)
        tgemm_pipe<2><<<dim3(DD / PBN, BT / PBM), 256, PIPE_SMEM>>>(
            y, outw + (size_t)l * DD * DD, nullptr, x, x, BT, DD, DD);
        // LN2
        ln_kernel<<<BT, 256>>>(x, ln2w + l * DD, ln2b + l * DD, h);
        // FFN1 + bias + exact GELU
        tgemm_pipe<1><<<dim3(FF / PBN, BT / PBM), 256, PIPE_SMEM>>>(
            h, w1 + (size_t)l * DD * FF, b1 + (size_t)l * FF, nullptr, f1, BT, FF, DD);
        // FFN2 + bias + residual (in-place on x)
        tgemm_pipe<3><<<dim3(DD / PBN, BT / PBM), 256, PIPE_SMEM>>>(
            f1, w2 + (size_t)l * FF * DD, b2 + (size_t)l * DD, x, x, BT, DD, FF);
    }

    // Final LN
    ln_kernel<<<BT, 256>>>(x, lnfw, lnfb, h);
    // Tied LM head: 3-term split-TF32 (near-exact), [2048,768] @ tok[1024,768]^T
    tgemm_split_tb<<<dim3(VV / BN, BT / BM), 256>>>(h, tok, out, BT, VV, DD);
}